// round 16
// baseline (speedup 1.0000x reference)
#include <cuda_runtime.h>
#include <cuda_fp16.h>
#include <cstddef>
#include <cstdint>
#include <math.h>

#define HWSZ 16384
#define IMG 128
#define CB 128
#define C3 384
#define BATCH 8
#define HEADS 8
#define KCH 32

typedef __half f16;

#define SA_ROW 40
#define SB_ROW 136
#define SA_PLANE (128 * SA_ROW)
#define SB_PLANE (32 * SB_ROW)
#define SA_ELEMS (4 * SA_PLANE)
#define SB_ELEMS (2 * SB_PLANE)
#define STG_H (SA_ELEMS + SB_ELEMS)
#define STG_BYTES (STG_H * 2)
#define QST_H (128 * 136)
#define QKG_BYTES ((STG_H + QST_H) * 2)

// ---------------- scratch ----------------
__device__ __align__(128) f16 g_xq16[(size_t)BATCH * C3 * HWSZ];
__device__ __align__(128) f16 g_D16[(size_t)BATCH * 3 * C3 * HWSZ];
__device__ __align__(128) f16 g_wqkv_h[C3 * CB], g_wqkv_l[C3 * CB];
__device__ __align__(128) f16 g_wq_h[CB * C3], g_wq_l[CB * C3];
__device__ __align__(128) f16 g_wk_h[CB * C3], g_wk_l[CB * C3];
__device__ __align__(128) f16 g_Mh[BATCH * CB * C3], g_Ml[BATCH * CB * C3];
__device__ float g_gram[BATCH * HEADS * 256];
__device__ float g_ssq[BATCH * HEADS * 16];
__device__ float g_ssk[BATCH * HEADS * 16];
__device__ float g_attn[BATCH * HEADS * 256];
__device__ float g_T1[BATCH * CB * C3];
__device__ float g_M[BATCH * CB * C3];

// ---------------- helpers ----------------
__device__ __forceinline__ uint32_t smem_u32(const void* p) {
    uint32_t a;
    asm("{ .reg .u64 t; cvta.to.shared.u64 t, %1; cvt.u32.u64 %0, t; }" : "=r"(a) : "l"(p));
    return a;
}
__device__ __forceinline__ void ldm_x4(uint32_t* r, uint32_t addr) {
    asm volatile("ldmatrix.sync.aligned.m8n8.x4.shared.b16 {%0,%1,%2,%3}, [%4];"
                 : "=r"(r[0]), "=r"(r[1]), "=r"(r[2]), "=r"(r[3]) : "r"(addr));
}
__device__ __forceinline__ void ldm_x2t(uint32_t* r, uint32_t addr) {
    asm volatile("ldmatrix.sync.aligned.m8n8.x2.trans.shared.b16 {%0,%1}, [%2];"
                 : "=r"(r[0]), "=r"(r[1]) : "r"(addr));
}
__device__ __forceinline__ void mma16816(float* d, const uint32_t* a, const uint32_t* b) {
    asm volatile(
        "mma.sync.aligned.m16n8k16.row.col.f32.f16.f16.f32 "
        "{%0,%1,%2,%3}, {%4,%5,%6,%7}, {%8,%9}, {%0,%1,%2,%3};"
        : "+f"(d[0]), "+f"(d[1]), "+f"(d[2]), "+f"(d[3])
        : "r"(a[0]), "r"(a[1]), "r"(a[2]), "r"(a[3]), "r"(b[0]), "r"(b[1]));
}
__device__ __forceinline__ uint4 load8f_cvt(const float* p) {
    float4 a = *(const float4*)p;
    float4 b = *(const float4*)(p + 4);
    f16 h[8] = {__float2half_rn(a.x), __float2half_rn(a.y), __float2half_rn(a.z),
                __float2half_rn(a.w), __float2half_rn(b.x), __float2half_rn(b.y),
                __float2half_rn(b.z), __float2half_rn(b.w)};
    return *(uint4*)h;
}

// ---- HMMA mainloop (proven) ----
template <bool BF32>
__device__ __forceinline__ void gemm_mainloop(
    const f16* __restrict__ Ahb, const f16* __restrict__ Alb, int Ktot, int m0,
    const void* __restrict__ Bb, size_t sStr, int n0,
    f16* sA, f16* sB, int tid, int wid, int lid, float acc[4][4][4]) {
    const int wm = (wid >> 2) * 64, wn = (wid & 3) * 32;
    const int nchunks = Ktot / KCH;
    const f16* B16 = (const f16*)Bb;
    const float* B32 = (const float*)Bb;

#pragma unroll
    for (int i = 0; i < 4; i++) {
        int u = tid + i * 256;
        int pl = u >> 9, v = u & 511;
        int m = v >> 2, kq = v & 3;
        const f16* src = (pl ? Alb : Ahb) + (size_t)(m0 + m) * Ktot + kq * 8;
        *(uint4*)(sA + pl * SA_PLANE + m * SA_ROW + kq * 8) = *(const uint4*)src;
    }
#pragma unroll
    for (int i = 0; i < 2; i++) {
        int u = tid + i * 256;
        int k = u >> 4, nu = u & 15;
        size_t off = (size_t)(k >> 7) * sStr + (size_t)(k & 127) * HWSZ + n0 + nu * 8;
        uint4 val;
        if (BF32) val = load8f_cvt(B32 + off);
        else      val = *(const uint4*)(B16 + off);
        *(uint4*)(sB + k * SB_ROW + nu * 8) = val;
    }
    __syncthreads();

    int buf = 0;
#pragma unroll 1
    for (int ch = 0; ch < nchunks; ch++) {
        const bool more = (ch + 1) < nchunks;
        uint4 pa[4], pb[2];
        if (more) {
            const int k0 = (ch + 1) * KCH;
#pragma unroll
            for (int i = 0; i < 4; i++) {
                int u = tid + i * 256;
                int pl = u >> 9, v = u & 511;
                int m = v >> 2, kq = v & 3;
                pa[i] = *(const uint4*)((pl ? Alb : Ahb) + (size_t)(m0 + m) * Ktot + k0 + kq * 8);
            }
#pragma unroll
            for (int i = 0; i < 2; i++) {
                int u = tid + i * 256;
                int k = u >> 4, nu = u & 15;
                int r = k0 + k;
                size_t off = (size_t)(r >> 7) * sStr + (size_t)(r & 127) * HWSZ + n0 + nu * 8;
                if (BF32) pb[i] = load8f_cvt(B32 + off);
                else      pb[i] = *(const uint4*)(B16 + off);
            }
        }

        const uint32_t aBase0 = smem_u32(sA + (buf * 2 + 0) * SA_PLANE);
        const uint32_t aBase1 = smem_u32(sA + (buf * 2 + 1) * SA_PLANE);
        const uint32_t bBase = smem_u32(sB + buf * SB_PLANE);
#pragma unroll
        for (int k16 = 0; k16 < 2; k16++) {
            const int kk = k16 * 16;
            uint32_t aF[2][4][4], bF[4][2];
            const uint32_t aOff =
                ((uint32_t)((wm + (lid & 15)) * SA_ROW + kk + ((lid >> 4) << 3))) * 2;
#pragma unroll
            for (int mb = 0; mb < 4; mb++) {
                ldm_x4(aF[0][mb], aBase0 + aOff + mb * 16 * SA_ROW * 2);
                ldm_x4(aF[1][mb], aBase1 + aOff + mb * 16 * SA_ROW * 2);
            }
            const uint32_t bOff = ((uint32_t)((kk + (lid & 15)) * SB_ROW + wn)) * 2;
#pragma unroll
            for (int nb = 0; nb < 4; nb++) ldm_x2t(bF[nb], bBase + bOff + nb * 16);
#pragma unroll
            for (int mb = 0; mb < 4; mb++)
#pragma unroll
                for (int nb = 0; nb < 4; nb++) {
                    mma16816(acc[mb][nb], aF[0][mb], bF[nb]);
                    mma16816(acc[mb][nb], aF[1][mb], bF[nb]);
                }
        }
        __syncthreads();

        if (more) {
            const int nb2 = buf ^ 1;
#pragma unroll
            for (int i = 0; i < 4; i++) {
                int u = tid + i * 256;
                int pl = u >> 9, v = u & 511;
                int m = v >> 2, kq = v & 3;
                *(uint4*)(sA + (nb2 * 2 + pl) * SA_PLANE + m * SA_ROW + kq * 8) = pa[i];
            }
#pragma unroll
            for (int i = 0; i < 2; i++) {
                int u = tid + i * 256;
                int k = u >> 4, nu = u & 15;
                *(uint4*)(sB + nb2 * SB_PLANE + k * SB_ROW + nu * 8) = pb[i];
            }
            __syncthreads();
            buf = nb2;
        }
    }
}

// ================= GEMM, fp32 output =================
__global__ void __launch_bounds__(256, 2)
tc_gemm_f32(const f16* __restrict__ Ah, const f16* __restrict__ Al, int Ktot, size_t aStr,
            const f16* __restrict__ B, size_t bStr, size_t sStr,
            float* __restrict__ C, size_t cStr) {
    extern __shared__ f16 dsm[];
    f16* sA = dsm;
    f16* sB = dsm + SA_ELEMS;
    const int tid = threadIdx.x, wid = tid >> 5, lid = tid & 31;
    const int m0 = blockIdx.x * 128, n0 = blockIdx.y * 128, b = blockIdx.z;
    const int wm = (wid >> 2) * 64, wn = (wid & 3) * 32;

    float acc[4][4][4];
#pragma unroll
    for (int i = 0; i < 4; i++)
#pragma unroll
        for (int j = 0; j < 4; j++)
#pragma unroll
            for (int t = 0; t < 4; t++) acc[i][j][t] = 0.f;

    gemm_mainloop<false>(Ah + (size_t)b * aStr, Al + (size_t)b * aStr, Ktot, m0,
                         B + (size_t)b * bStr, sStr, n0, sA, sB, tid, wid, lid, acc);

    float* Cp = C + (size_t)b * cStr;
    const int g = lid >> 2, t = lid & 3;
#pragma unroll
    for (int mb = 0; mb < 4; mb++)
#pragma unroll
        for (int nb = 0; nb < 4; nb++) {
            int m = m0 + wm + mb * 16 + g;
            int n = n0 + wn + nb * 8 + t * 2;
            *(float2*)&Cp[(size_t)m * HWSZ + n] = make_float2(acc[mb][nb][0], acc[mb][nb][1]);
            *(float2*)&Cp[(size_t)(m + 8) * HWSZ + n] = make_float2(acc[mb][nb][2], acc[mb][nb][3]);
        }
}

// ================= GEMM, fp16 output, fp32 B =================
__global__ void __launch_bounds__(256, 2)
tc_gemm_f16_bf32(const f16* __restrict__ Ah, const f16* __restrict__ Al, int Ktot, size_t aStr,
                 const float* __restrict__ B, size_t bStr, size_t sStr,
                 f16* __restrict__ C, size_t cStr) {
    extern __shared__ f16 dsm[];
    f16* sA = dsm;
    f16* sB = dsm + SA_ELEMS;
    const int tid = threadIdx.x, wid = tid >> 5, lid = tid & 31;
    const int m0 = blockIdx.x * 128, n0 = blockIdx.y * 128, b = blockIdx.z;
    const int wm = (wid >> 2) * 64, wn = (wid & 3) * 32;

    float acc[4][4][4];
#pragma unroll
    for (int i = 0; i < 4; i++)
#pragma unroll
        for (int j = 0; j < 4; j++)
#pragma unroll
            for (int t = 0; t < 4; t++) acc[i][j][t] = 0.f;

    gemm_mainloop<true>(Ah + (size_t)b * aStr, Al + (size_t)b * aStr, Ktot, m0,
                        B + (size_t)b * bStr, sStr, n0, sA, sB, tid, wid, lid, acc);

    f16* Cp = C + (size_t)b * cStr;
    const int g = lid >> 2, t = lid & 3;
#pragma unroll
    for (int mb = 0; mb < 4; mb++)
#pragma unroll
        for (int nb = 0; nb < 4; nb++) {
            int m = m0 + wm + mb * 16 + g;
            int n = n0 + wn + nb * 8 + t * 2;
            __half2 v01 = __floats2half2_rn(acc[mb][nb][0], acc[mb][nb][1]);
            __half2 v23 = __floats2half2_rn(acc[mb][nb][2], acc[mb][nb][3]);
            *(__half2*)&Cp[(size_t)m * HWSZ + n] = v01;
            *(__half2*)&Cp[(size_t)(m + 8) * HWSZ + n] = v23;
        }
}

// ====== fused q-proj + k-proj + per-head gram/sumsq ======
__global__ void __launch_bounds__(256, 2)
qk_gram(const f16* __restrict__ wqh, const f16* __restrict__ wql,
        const f16* __restrict__ wkh, const f16* __restrict__ wkl,
        const f16* __restrict__ D,
        float* __restrict__ G, float* __restrict__ SQ, float* __restrict__ SK) {
    extern __shared__ f16 dsm[];
    f16* sA = dsm;
    f16* sB = dsm + SA_ELEMS;
    f16* qsth = dsm + STG_H;
    f16* ksth = dsm;

    const int tid = threadIdx.x, wid = tid >> 5, lid = tid & 31;
    const int n0 = blockIdx.x * 128, b = blockIdx.y;
    const int wm = (wid >> 2) * 64, wn = (wid & 3) * 32;
    const int g = lid >> 2, t4 = lid & 3;

    const f16* Db = D + (size_t)b * 3 * C3 * HWSZ;

    float acc[4][4][4];
#pragma unroll
    for (int i = 0; i < 4; i++)
#pragma unroll
        for (int j = 0; j < 4; j++)
#pragma unroll
            for (int t = 0; t < 4; t++) acc[i][j][t] = 0.f;

    gemm_mainloop<false>(wqh, wql, C3, 0, Db, (size_t)C3 * HWSZ, n0,
                         sA, sB, tid, wid, lid, acc);
#pragma unroll
    for (int mb = 0; mb < 4; mb++)
#pragma unroll
        for (int nb = 0; nb < 4; nb++) {
            int m = wm + mb * 16 + g;
            int n = wn + nb * 8 + t4 * 2;
            qsth[n * 136 + m] = __float2half_rn(acc[mb][nb][0]);
            qsth[(n + 1) * 136 + m] = __float2half_rn(acc[mb][nb][1]);
            qsth[n * 136 + m + 8] = __float2half_rn(acc[mb][nb][2]);
            qsth[(n + 1) * 136 + m + 8] = __float2half_rn(acc[mb][nb][3]);
            acc[mb][nb][0] = acc[mb][nb][1] = acc[mb][nb][2] = acc[mb][nb][3] = 0.f;
        }
    __syncthreads();

    gemm_mainloop<false>(wkh, wkl, C3, 0, Db + (size_t)CB * HWSZ, (size_t)C3 * HWSZ, n0,
                         sA, sB, tid, wid, lid, acc);
    __syncthreads();
#pragma unroll
    for (int mb = 0; mb < 4; mb++)
#pragma unroll
        for (int nb = 0; nb < 4; nb++) {
            int m = wm + mb * 16 + g;
            int n = wn + nb * 8 + t4 * 2;
            ksth[n * 136 + m] = __float2half_rn(acc[mb][nb][0]);
            ksth[(n + 1) * 136 + m] = __float2half_rn(acc[mb][nb][1]);
            ksth[n * 136 + m + 8] = __float2half_rn(acc[mb][nb][2]);
            ksth[(n + 1) * 136 + m + 8] = __float2half_rn(acc[mb][nb][3]);
        }
    __syncthreads();

    {
        const int h = wid;
        const int c = lid >> 1;
        const int d0 = (lid & 1) * 8;
        float a8[8] = {0, 0, 0, 0, 0, 0, 0, 0};
        float sq = 0.f, sk8[8] = {0, 0, 0, 0, 0, 0, 0, 0};
#pragma unroll 4
        for (int n = 0; n < 128; n++) {
            float qv = __half2float(qsth[n * 136 + h * 16 + c]);
            uint4 kvu = *(const uint4*)&ksth[n * 136 + h * 16 + d0];
            __half2* kh2 = (__half2*)&kvu;
            float2 k01 = __half22float2(kh2[0]);
            float2 k23 = __half22float2(kh2[1]);
            float2 k45 = __half22float2(kh2[2]);
            float2 k67 = __half22float2(kh2[3]);
            a8[0] += qv * k01.x; a8[1] += qv * k01.y;
            a8[2] += qv * k23.x; a8[3] += qv * k23.y;
            a8[4] += qv * k45.x; a8[5] += qv * k45.y;
            a8[6] += qv * k67.x; a8[7] += qv * k67.y;
            if ((lid & 1) == 0) sq += qv * qv;
            if (c == 0) {
                sk8[0] += k01.x * k01.x; sk8[1] += k01.y * k01.y;
                sk8[2] += k23.x * k23.x; sk8[3] += k23.y * k23.y;
                sk8[4] += k45.x * k45.x; sk8[5] += k45.y * k45.y;
                sk8[6] += k67.x * k67.x; sk8[7] += k67.y * k67.y;
            }
        }
        const int bh = b * HEADS + h;
#pragma unroll
        for (int j = 0; j < 8; j++)
            atomicAdd(&G[(size_t)bh * 256 + c * 16 + d0 + j], a8[j]);
        if ((lid & 1) == 0) atomicAdd(&SQ[bh * 16 + c], sq);
        if (c == 0)
#pragma unroll
            for (int j = 0; j < 8; j++) atomicAdd(&SK[bh * 16 + d0 + j], sk8[j]);
    }
}

// ---------------- prep kernels ----------------
__device__ __forceinline__ void split_store(const float4& v, f16* hi, f16* lo, int i) {
    float a[4] = {v.x, v.y, v.z, v.w};
    f16 h[4], l[4];
#pragma unroll
    for (int j = 0; j < 4; j++) {
        h[j] = __float2half_rn(a[j]);
        l[j] = __float2half_rn(a[j] - __half2float(h[j]));
    }
    ((uint2*)hi)[i] = *(uint2*)h;
    ((uint2*)lo)[i] = *(uint2*)l;
}

__global__ void prep_w(const float* __restrict__ wqkv, const float* __restrict__ wq,
                       const float* __restrict__ wk,
                       f16* __restrict__ qkvh, f16* __restrict__ qkvl,
                       f16* __restrict__ qh, f16* __restrict__ ql,
                       f16* __restrict__ kh, f16* __restrict__ kl) {
    int i = blockIdx.x * 256 + threadIdx.x;
    const int n4 = C3 * CB / 4;
    if (i >= n4) return;
    if (blockIdx.y == 0)      split_store(((const float4*)wqkv)[i], qkvh, qkvl, i);
    else if (blockIdx.y == 1) split_store(((const float4*)wq)[i], qh, ql, i);
    else                      split_store(((const float4*)wk)[i], kh, kl, i);
}

__global__ void zero_stats(float* __restrict__ G, float* __restrict__ SQ,
                           float* __restrict__ SK) {
    int i = blockIdx.x * 256 + threadIdx.x;
    if (i < BATCH * HEADS * 256) G[i] = 0.f;
    if (i < BATCH * HEADS * 16) { SQ[i] = 0.f; SK[i] = 0.f; }
}

__global__ void cvt_split_h(const float* __restrict__ src, f16* __restrict__ hi,
                            f16* __restrict__ lo, int n4) {
    int i = blockIdx.x * 256 + threadIdx.x;
    if (i >= n4) return;
    split_store(((const float4*)src)[i], hi, lo, i);
}

// ----- dwconv: scalar FFMA, 2-row blocking, channel-range parameterized -----
__global__ void __launch_bounds__(256)
dwconv_kernel(const f16* __restrict__ xq, const float* __restrict__ w3,
              const float* __restrict__ w5, const float* __restrict__ w7,
              f16* __restrict__ D, int coff, int nch) {
    __shared__ float tile[38][72];
    __shared__ float s3[9], s5[25], s7[49];

    const int bc = blockIdx.z;
    const int b = bc / nch, c = coff + (bc % nch);
    const int x0 = blockIdx.x * 64, y0 = blockIdx.y * 32;
    const int tid = threadIdx.x;

    const f16* src = xq + ((size_t)b * C3 + c) * HWSZ;
    if (tid < 9)  s3[tid] = w3[c * 9 + tid];
    if (tid < 25) s5[tid] = w5[c * 25 + tid];
    if (tid < 49) s7[tid] = w7[c * 49 + tid];

    for (int e = tid; e < 38 * 70; e += 256) {
        int iy = e / 70, ix = e % 70;
        int gy = y0 - 3 + iy, gx = x0 - 3 + ix;
        float v = 0.f;
        if (gy >= 0 && gy < IMG && gx >= 0 && gx < IMG) v = __half2float(src[gy * IMG + gx]);
        tile[iy][ix] = v;
    }
    __syncthreads();

    const int tx = (tid & 15) * 4;
    const int ty = (tid >> 4) * 2;

    float a3[2][4], a5[2][4], a7[2][4];
#pragma unroll
    for (int r = 0; r < 2; r++)
#pragma unroll
        for (int xi = 0; xi < 4; xi++) { a3[r][xi] = 0.f; a5[r][xi] = 0.f; a7[r][xi] = 0.f; }

#pragma unroll
    for (int iy = 0; iy < 8; iy++) {
        float rr[10];
#pragma unroll
        for (int j = 0; j < 10; j++) rr[j] = tile[ty + iy][tx + j];
#pragma unroll
        for (int orow = 0; orow < 2; orow++) {
            const int ky = iy - orow;
            if (ky >= 0 && ky <= 6) {
#pragma unroll
                for (int kx = 0; kx < 7; kx++) {
                    float w = s7[ky * 7 + kx];
#pragma unroll
                    for (int xi = 0; xi < 4; xi++) a7[orow][xi] += rr[kx + xi] * w;
                }
                if (ky >= 1 && ky <= 5) {
#pragma unroll
                    for (int kx = 0; kx < 5; kx++) {
                        float w = s5[(ky - 1) * 5 + kx];
#pragma unroll
                        for (int xi = 0; xi < 4; xi++) a5[orow][xi] += rr[kx + 1 + xi] * w;
                    }
                }
                if (ky >= 2 && ky <= 4) {
#pragma unroll
                    for (int kx = 0; kx < 3; kx++) {
                        float w = s3[(ky - 2) * 3 + kx];
#pragma unroll
                        for (int xi = 0; xi < 4; xi++) a3[orow][xi] += rr[kx + 2 + xi] * w;
                    }
                }
            }
        }
    }

#pragma unroll
    for (int orow = 0; orow < 2; orow++) {
        size_t o = ((size_t)b * 3 * C3 + c) * HWSZ +
                   (size_t)(y0 + ty + orow) * IMG + (x0 + tx);
        f16 h3[4] = {__float2half_rn(a3[orow][0]), __float2half_rn(a3[orow][1]),
                     __float2half_rn(a3[orow][2]), __float2half_rn(a3[orow][3])};
        f16 h5[4] = {__float2half_rn(a5[orow][0]), __float2half_rn(a5[orow][1]),
                     __float2half_rn(a5[orow][2]), __float2half_rn(a5[orow][3])};
        f16 h7[4] = {__float2half_rn(a7[orow][0]), __float2half_rn(a7[orow][1]),
                     __float2half_rn(a7[orow][2]), __float2half_rn(a7[orow][3])};
        *(uint2*)&D[o] = *(uint2*)h3;
        *(uint2*)&D[o + (size_t)C3 * HWSZ] = *(uint2*)h5;
        *(uint2*)&D[o + (size_t)2 * C3 * HWSZ] = *(uint2*)h7;
    }
}

// ---------------- softmax finalize ----------------
__global__ void attn_finalize(const float* __restrict__ G, const float* __restrict__ SQ,
                              const float* __restrict__ SK, const float* __restrict__ temp,
                              float* __restrict__ attn) {
    const int bh = blockIdx.x, h = bh & 7, c = threadIdx.x;
    if (c >= 16) return;
    float nq = fmaxf(sqrtf(SQ[bh * 16 + c]), 1e-12f);
    float t = temp[h];
    float s[16], mx = -1e30f;
#pragma unroll
    for (int d = 0; d < 16; d++) {
        float nk = fmaxf(sqrtf(SK[bh * 16 + d]), 1e-12f);
        s[d] = G[bh * 256 + c * 16 + d] / (nq * nk) * t;
        mx = fmaxf(mx, s[d]);
    }
    float sum = 0.f;
#pragma unroll
    for (int d = 0; d < 16; d++) { s[d] = expf(s[d] - mx); sum += s[d]; }
    float inv = 1.f / sum;
#pragma unroll
    for (int d = 0; d < 16; d++) attn[bh * 256 + c * 16 + d] = s[d] * inv;
}

// ---------------- T1 / M ----------------
__global__ void t1_kernel(const float* __restrict__ attn, const float* __restrict__ wv,
                          float* __restrict__ T1) {
    const int bm = blockIdx.x, b = bm >> 7, m = bm & 127, h = m >> 4, cm = m & 15;
    __shared__ float a[16];
    if (threadIdx.x < 16) a[threadIdx.x] = attn[((b * 8 + h) * 16 + cm) * 16 + threadIdx.x];
    __syncthreads();
    const int r = threadIdx.x;
    float acc = 0.f;
#pragma unroll
    for (int d = 0; d < 16; d++) acc += a[d] * wv[(h * 16 + d) * C3 + r];
    T1[((size_t)b * CB + m) * C3 + r] = acc;
}

__global__ void m_kernel(const float* __restrict__ wout, const float* __restrict__ T1,
                         float* __restrict__ Mo) {
    const int bo = blockIdx.x, b = bo >> 7, o = bo & 127;
    __shared__ float w[128];
    if (threadIdx.x < 128) w[threadIdx.x] = wout[o * 128 + threadIdx.x];
    __syncthreads();
    const int r = threadIdx.x;
    float acc = 0.f;
#pragma unroll 8
    for (int m = 0; m < 128; m++) acc += w[m] * T1[((size_t)b * CB + m) * C3 + r];
    Mo[((size_t)b * CB + o) * C3 + r] = acc;
}

// ---------------- host launcher ----------------
extern "C" void kernel_launch(void* const* d_in, const int* in_sizes, int n_in,
                              void* d_out, int out_size) {
    const float* x     = (const float*)d_in[0];
    const float* w_qkv = (const float*)d_in[1];
    const float* w_dw3 = (const float*)d_in[2];
    const float* w_dw5 = (const float*)d_in[3];
    const float* w_dw7 = (const float*)d_in[4];
    const float* w_q   = (const float*)d_in[5];
    const float* w_k   = (const float*)d_in[6];
    const float* w_v   = (const float*)d_in[7];
    const float* w_out = (const float*)d_in[8];
    const float* temp  = (const float*)d_in[9];
    float* out = (float*)d_out;

    float *p_gram, *p_ssq, *p_ssk, *p_attn, *p_T1, *p_M;
    f16 *p_xq16, *p_D16, *p_wqkvh, *p_wqkvl, *p_wqh, *p_wql, *p_wkh, *p_wkl, *p_Mh, *p_Ml;
    cudaGetSymbolAddress((void**)&p_xq16, g_xq16);
    cudaGetSymbolAddress((void**)&p_D16, g_D16);
    cudaGetSymbolAddress((void**)&p_gram, g_gram);
    cudaGetSymbolAddress((void**)&p_ssq, g_ssq);
    cudaGetSymbolAddress((void**)&p_ssk, g_ssk);
    cudaGetSymbolAddress((void**)&p_attn, g_attn);
    cudaGetSymbolAddress((void**)&p_T1, g_T1);
    cudaGetSymbolAddress((void**)&p_M, g_M);
    cudaGetSymbolAddress((void**)&p_wqkvh, g_wqkv_h);
    cudaGetSymbolAddress((void**)&p_wqkvl, g_wqkv_l);
    cudaGetSymbolAddress((void**)&p_wqh, g_wq_h);
    cudaGetSymbolAddress((void**)&p_wql, g_wq_l);
    cudaGetSymbolAddress((void**)&p_wkh, g_wk_h);
    cudaGetSymbolAddress((void**)&p_wkl, g_wk_l);
    cudaGetSymbolAddress((void**)&p_Mh, g_Mh);
    cudaGetSymbolAddress((void**)&p_Ml, g_Ml);

    cudaFuncSetAttribute(tc_gemm_f32, cudaFuncAttributeMaxDynamicSharedMemorySize, STG_BYTES);
    cudaFuncSetAttribute(tc_gemm_f16_bf32, cudaFuncAttributeMaxDynamicSharedMemorySize, STG_BYTES);
    cudaFuncSetAttribute(qk_gram, cudaFuncAttributeMaxDynamicSharedMemorySize, QKG_BYTES);

    // lazily created side stream + fork/join events (identical work every call)
    static cudaStream_t s2 = nullptr;
    static cudaEvent_t ev1 = nullptr, ev2 = nullptr;
    if (s2 == nullptr) {
        cudaStreamCreateWithFlags(&s2, cudaStreamNonBlocking);
        cudaEventCreateWithFlags(&ev1, cudaEventDisableTiming);
        cudaEventCreateWithFlags(&ev2, cudaEventDisableTiming);
    }

    prep_w<<<dim3(48, 3), 256>>>(w_qkv, w_q, w_k, p_wqkvh, p_wqkvl,
                                 p_wqh, p_wql, p_wkh, p_wkl);
    zero_stats<<<64, 256>>>(p_gram, p_ssq, p_ssk);

    // 1) xq = w_qkv @ x
    tc_gemm_f16_bf32<<<dim3(3, 128, BATCH), 256, STG_BYTES>>>(
        p_wqkvh, p_wqkvl, 128, (size_t)0,
        x, (size_t)CB * HWSZ, (size_t)CB * HWSZ,
        p_xq16, (size_t)C3 * HWSZ);

    // 2a) dwconv for q,k channels (0..255) on main stream
    dwconv_kernel<<<dim3(2, 4, BATCH * 256), 256>>>(
        p_xq16, w_dw3, w_dw5, w_dw7, p_D16, 0, 256);

    // fork: v-channel dwconv runs on s2 concurrent with qk_gram
    cudaEventRecord(ev1, 0);
    cudaStreamWaitEvent(s2, ev1, 0);
    dwconv_kernel<<<dim3(2, 4, BATCH * 128), 256, 0, s2>>>(
        p_xq16, w_dw3, w_dw5, w_dw7, p_D16, 256, 128);
    cudaEventRecord(ev2, s2);

    // 3) fused q/k projections + gram + sumsq (needs only channels 0..255)
    qk_gram<<<dim3(128, BATCH), 256, QKG_BYTES>>>(
        p_wqh, p_wql, p_wkh, p_wkl, p_D16, p_gram, p_ssq, p_ssk);

    attn_finalize<<<BATCH * HEADS, 32>>>(p_gram, p_ssq, p_ssk, temp, p_attn);

    // 4) M_b -> fp16 split
    t1_kernel<<<BATCH * CB, 384>>>(p_attn, w_v, p_T1);
    m_kernel<<<BATCH * CB, 384>>>(w_out, p_T1, p_M);
    cvt_split_h<<<384, 256>>>(p_M, p_Mh, p_Ml, BATCH * CB * C3 / 4);

    // join: out-gemm needs v channels of D
    cudaStreamWaitEvent(0, ev2, 0);

    // 5) out = M_b @ D(v-part)
    tc_gemm_f32<<<dim3(1, 128, BATCH), 256, STG_BYTES>>>(
        p_Mh, p_Ml, 384, (size_t)CB * C3,
        p_D16 + (size_t)2 * CB * HWSZ, (size_t)3 * C3 * HWSZ, (size_t)C3 * HWSZ,
        out, (size_t)CB * HWSZ);
}

// round 17
// speedup vs baseline: 1.0270x; 1.0270x over previous
#include <cuda_runtime.h>
#include <cuda_fp16.h>
#include <cstddef>
#include <cstdint>
#include <math.h>

#define HWSZ 16384
#define IMG 128
#define CB 128
#define C3 384
#define BATCH 8
#define HEADS 8
#define KCH 32

typedef __half f16;

#define SA_ROW 40
#define SB_ROW 136
#define SA_PLANE (128 * SA_ROW)
#define SB_PLANE (32 * SB_ROW)
#define SA_ELEMS (4 * SA_PLANE)
#define SB_ELEMS (2 * SB_PLANE)
#define STG_H (SA_ELEMS + SB_ELEMS)
#define STG_BYTES (STG_H * 2)
#define QST_H (128 * 136)
#define QKG_BYTES ((STG_H + QST_H) * 2)

// ---------------- scratch ----------------
__device__ __align__(128) f16 g_xq16[(size_t)BATCH * C3 * HWSZ];
__device__ __align__(128) f16 g_D16[(size_t)BATCH * 3 * C3 * HWSZ];
__device__ __align__(128) f16 g_wqkv_h[C3 * CB], g_wqkv_l[C3 * CB];
__device__ __align__(128) f16 g_wq_h[CB * C3], g_wq_l[CB * C3];
__device__ __align__(128) f16 g_wk_h[CB * C3], g_wk_l[CB * C3];
__device__ __align__(128) f16 g_Mh[BATCH * CB * C3], g_Ml[BATCH * CB * C3];
__device__ float g_gram[BATCH * HEADS * 256];
__device__ float g_ssq[BATCH * HEADS * 16];
__device__ float g_ssk[BATCH * HEADS * 16];
__device__ float g_T1[BATCH * CB * C3];

// ---------------- helpers ----------------
__device__ __forceinline__ uint32_t smem_u32(const void* p) {
    uint32_t a;
    asm("{ .reg .u64 t; cvta.to.shared.u64 t, %1; cvt.u32.u64 %0, t; }" : "=r"(a) : "l"(p));
    return a;
}
__device__ __forceinline__ void ldm_x4(uint32_t* r, uint32_t addr) {
    asm volatile("ldmatrix.sync.aligned.m8n8.x4.shared.b16 {%0,%1,%2,%3}, [%4];"
                 : "=r"(r[0]), "=r"(r[1]), "=r"(r[2]), "=r"(r[3]) : "r"(addr));
}
__device__ __forceinline__ void ldm_x2t(uint32_t* r, uint32_t addr) {
    asm volatile("ldmatrix.sync.aligned.m8n8.x2.trans.shared.b16 {%0,%1}, [%2];"
                 : "=r"(r[0]), "=r"(r[1]) : "r"(addr));
}
__device__ __forceinline__ void mma16816(float* d, const uint32_t* a, const uint32_t* b) {
    asm volatile(
        "mma.sync.aligned.m16n8k16.row.col.f32.f16.f16.f32 "
        "{%0,%1,%2,%3}, {%4,%5,%6,%7}, {%8,%9}, {%0,%1,%2,%3};"
        : "+f"(d[0]), "+f"(d[1]), "+f"(d[2]), "+f"(d[3])
        : "r"(a[0]), "r"(a[1]), "r"(a[2]), "r"(a[3]), "r"(b[0]), "r"(b[1]));
}
__device__ __forceinline__ uint4 load8f_cvt(const float* p) {
    float4 a = *(const float4*)p;
    float4 b = *(const float4*)(p + 4);
    f16 h[8] = {__float2half_rn(a.x), __float2half_rn(a.y), __float2half_rn(a.z),
                __float2half_rn(a.w), __float2half_rn(b.x), __float2half_rn(b.y),
                __float2half_rn(b.z), __float2half_rn(b.w)};
    return *(uint4*)h;
}

// ---- HMMA mainloop (proven) ----
template <bool BF32>
__device__ __forceinline__ void gemm_mainloop(
    const f16* __restrict__ Ahb, const f16* __restrict__ Alb, int Ktot, int m0,
    const void* __restrict__ Bb, size_t sStr, int n0,
    f16* sA, f16* sB, int tid, int wid, int lid, float acc[4][4][4]) {
    const int wm = (wid >> 2) * 64, wn = (wid & 3) * 32;
    const int nchunks = Ktot / KCH;
    const f16* B16 = (const f16*)Bb;
    const float* B32 = (const float*)Bb;

#pragma unroll
    for (int i = 0; i < 4; i++) {
        int u = tid + i * 256;
        int pl = u >> 9, v = u & 511;
        int m = v >> 2, kq = v & 3;
        const f16* src = (pl ? Alb : Ahb) + (size_t)(m0 + m) * Ktot + kq * 8;
        *(uint4*)(sA + pl * SA_PLANE + m * SA_ROW + kq * 8) = *(const uint4*)src;
    }
#pragma unroll
    for (int i = 0; i < 2; i++) {
        int u = tid + i * 256;
        int k = u >> 4, nu = u & 15;
        size_t off = (size_t)(k >> 7) * sStr + (size_t)(k & 127) * HWSZ + n0 + nu * 8;
        uint4 val;
        if (BF32) val = load8f_cvt(B32 + off);
        else      val = *(const uint4*)(B16 + off);
        *(uint4*)(sB + k * SB_ROW + nu * 8) = val;
    }
    __syncthreads();

    int buf = 0;
#pragma unroll 1
    for (int ch = 0; ch < nchunks; ch++) {
        const bool more = (ch + 1) < nchunks;
        uint4 pa[4], pb[2];
        if (more) {
            const int k0 = (ch + 1) * KCH;
#pragma unroll
            for (int i = 0; i < 4; i++) {
                int u = tid + i * 256;
                int pl = u >> 9, v = u & 511;
                int m = v >> 2, kq = v & 3;
                pa[i] = *(const uint4*)((pl ? Alb : Ahb) + (size_t)(m0 + m) * Ktot + k0 + kq * 8);
            }
#pragma unroll
            for (int i = 0; i < 2; i++) {
                int u = tid + i * 256;
                int k = u >> 4, nu = u & 15;
                int r = k0 + k;
                size_t off = (size_t)(r >> 7) * sStr + (size_t)(r & 127) * HWSZ + n0 + nu * 8;
                if (BF32) pb[i] = load8f_cvt(B32 + off);
                else      pb[i] = *(const uint4*)(B16 + off);
            }
        }

        const uint32_t aBase0 = smem_u32(sA + (buf * 2 + 0) * SA_PLANE);
        const uint32_t aBase1 = smem_u32(sA + (buf * 2 + 1) * SA_PLANE);
        const uint32_t bBase = smem_u32(sB + buf * SB_PLANE);
#pragma unroll
        for (int k16 = 0; k16 < 2; k16++) {
            const int kk = k16 * 16;
            uint32_t aF[2][4][4], bF[4][2];
            const uint32_t aOff =
                ((uint32_t)((wm + (lid & 15)) * SA_ROW + kk + ((lid >> 4) << 3))) * 2;
#pragma unroll
            for (int mb = 0; mb < 4; mb++) {
                ldm_x4(aF[0][mb], aBase0 + aOff + mb * 16 * SA_ROW * 2);
                ldm_x4(aF[1][mb], aBase1 + aOff + mb * 16 * SA_ROW * 2);
            }
            const uint32_t bOff = ((uint32_t)((kk + (lid & 15)) * SB_ROW + wn)) * 2;
#pragma unroll
            for (int nb = 0; nb < 4; nb++) ldm_x2t(bF[nb], bBase + bOff + nb * 16);
#pragma unroll
            for (int mb = 0; mb < 4; mb++)
#pragma unroll
                for (int nb = 0; nb < 4; nb++) {
                    mma16816(acc[mb][nb], aF[0][mb], bF[nb]);
                    mma16816(acc[mb][nb], aF[1][mb], bF[nb]);
                }
        }
        __syncthreads();

        if (more) {
            const int nb2 = buf ^ 1;
#pragma unroll
            for (int i = 0; i < 4; i++) {
                int u = tid + i * 256;
                int pl = u >> 9, v = u & 511;
                int m = v >> 2, kq = v & 3;
                *(uint4*)(sA + (nb2 * 2 + pl) * SA_PLANE + m * SA_ROW + kq * 8) = pa[i];
            }
#pragma unroll
            for (int i = 0; i < 2; i++) {
                int u = tid + i * 256;
                int k = u >> 4, nu = u & 15;
                *(uint4*)(sB + nb2 * SB_PLANE + k * SB_ROW + nu * 8) = pb[i];
            }
            __syncthreads();
            buf = nb2;
        }
    }
}

// ================= GEMM, fp32 output =================
__global__ void __launch_bounds__(256, 2)
tc_gemm_f32(const f16* __restrict__ Ah, const f16* __restrict__ Al, int Ktot, size_t aStr,
            const f16* __restrict__ B, size_t bStr, size_t sStr,
            float* __restrict__ C, size_t cStr) {
    extern __shared__ f16 dsm[];
    f16* sA = dsm;
    f16* sB = dsm + SA_ELEMS;
    const int tid = threadIdx.x, wid = tid >> 5, lid = tid & 31;
    const int m0 = blockIdx.x * 128, n0 = blockIdx.y * 128, b = blockIdx.z;
    const int wm = (wid >> 2) * 64, wn = (wid & 3) * 32;

    float acc[4][4][4];
#pragma unroll
    for (int i = 0; i < 4; i++)
#pragma unroll
        for (int j = 0; j < 4; j++)
#pragma unroll
            for (int t = 0; t < 4; t++) acc[i][j][t] = 0.f;

    gemm_mainloop<false>(Ah + (size_t)b * aStr, Al + (size_t)b * aStr, Ktot, m0,
                         B + (size_t)b * bStr, sStr, n0, sA, sB, tid, wid, lid, acc);

    float* Cp = C + (size_t)b * cStr;
    const int g = lid >> 2, t = lid & 3;
#pragma unroll
    for (int mb = 0; mb < 4; mb++)
#pragma unroll
        for (int nb = 0; nb < 4; nb++) {
            int m = m0 + wm + mb * 16 + g;
            int n = n0 + wn + nb * 8 + t * 2;
            *(float2*)&Cp[(size_t)m * HWSZ + n] = make_float2(acc[mb][nb][0], acc[mb][nb][1]);
            *(float2*)&Cp[(size_t)(m + 8) * HWSZ + n] = make_float2(acc[mb][nb][2], acc[mb][nb][3]);
        }
}

// ================= GEMM, fp16 output, fp32 B =================
__global__ void __launch_bounds__(256, 2)
tc_gemm_f16_bf32(const f16* __restrict__ Ah, const f16* __restrict__ Al, int Ktot, size_t aStr,
                 const float* __restrict__ B, size_t bStr, size_t sStr,
                 f16* __restrict__ C, size_t cStr) {
    extern __shared__ f16 dsm[];
    f16* sA = dsm;
    f16* sB = dsm + SA_ELEMS;
    const int tid = threadIdx.x, wid = tid >> 5, lid = tid & 31;
    const int m0 = blockIdx.x * 128, n0 = blockIdx.y * 128, b = blockIdx.z;
    const int wm = (wid >> 2) * 64, wn = (wid & 3) * 32;

    float acc[4][4][4];
#pragma unroll
    for (int i = 0; i < 4; i++)
#pragma unroll
        for (int j = 0; j < 4; j++)
#pragma unroll
            for (int t = 0; t < 4; t++) acc[i][j][t] = 0.f;

    gemm_mainloop<true>(Ah + (size_t)b * aStr, Al + (size_t)b * aStr, Ktot, m0,
                        B + (size_t)b * bStr, sStr, n0, sA, sB, tid, wid, lid, acc);

    f16* Cp = C + (size_t)b * cStr;
    const int g = lid >> 2, t = lid & 3;
#pragma unroll
    for (int mb = 0; mb < 4; mb++)
#pragma unroll
        for (int nb = 0; nb < 4; nb++) {
            int m = m0 + wm + mb * 16 + g;
            int n = n0 + wn + nb * 8 + t * 2;
            __half2 v01 = __floats2half2_rn(acc[mb][nb][0], acc[mb][nb][1]);
            __half2 v23 = __floats2half2_rn(acc[mb][nb][2], acc[mb][nb][3]);
            *(__half2*)&Cp[(size_t)m * HWSZ + n] = v01;
            *(__half2*)&Cp[(size_t)(m + 8) * HWSZ + n] = v23;
        }
}

// ====== fused q-proj + k-proj + per-head gram/sumsq ======
__global__ void __launch_bounds__(256, 2)
qk_gram(const f16* __restrict__ wqh, const f16* __restrict__ wql,
        const f16* __restrict__ wkh, const f16* __restrict__ wkl,
        const f16* __restrict__ D,
        float* __restrict__ G, float* __restrict__ SQ, float* __restrict__ SK) {
    extern __shared__ f16 dsm[];
    f16* sA = dsm;
    f16* sB = dsm + SA_ELEMS;
    f16* qsth = dsm + STG_H;
    f16* ksth = dsm;

    const int tid = threadIdx.x, wid = tid >> 5, lid = tid & 31;
    const int n0 = blockIdx.x * 128, b = blockIdx.y;
    const int wm = (wid >> 2) * 64, wn = (wid & 3) * 32;
    const int g = lid >> 2, t4 = lid & 3;

    const f16* Db = D + (size_t)b * 3 * C3 * HWSZ;

    float acc[4][4][4];
#pragma unroll
    for (int i = 0; i < 4; i++)
#pragma unroll
        for (int j = 0; j < 4; j++)
#pragma unroll
            for (int t = 0; t < 4; t++) acc[i][j][t] = 0.f;

    gemm_mainloop<false>(wqh, wql, C3, 0, Db, (size_t)C3 * HWSZ, n0,
                         sA, sB, tid, wid, lid, acc);
#pragma unroll
    for (int mb = 0; mb < 4; mb++)
#pragma unroll
        for (int nb = 0; nb < 4; nb++) {
            int m = wm + mb * 16 + g;
            int n = wn + nb * 8 + t4 * 2;
            qsth[n * 136 + m] = __float2half_rn(acc[mb][nb][0]);
            qsth[(n + 1) * 136 + m] = __float2half_rn(acc[mb][nb][1]);
            qsth[n * 136 + m + 8] = __float2half_rn(acc[mb][nb][2]);
            qsth[(n + 1) * 136 + m + 8] = __float2half_rn(acc[mb][nb][3]);
            acc[mb][nb][0] = acc[mb][nb][1] = acc[mb][nb][2] = acc[mb][nb][3] = 0.f;
        }
    __syncthreads();

    gemm_mainloop<false>(wkh, wkl, C3, 0, Db + (size_t)CB * HWSZ, (size_t)C3 * HWSZ, n0,
                         sA, sB, tid, wid, lid, acc);
    __syncthreads();
#pragma unroll
    for (int mb = 0; mb < 4; mb++)
#pragma unroll
        for (int nb = 0; nb < 4; nb++) {
            int m = wm + mb * 16 + g;
            int n = wn + nb * 8 + t4 * 2;
            ksth[n * 136 + m] = __float2half_rn(acc[mb][nb][0]);
            ksth[(n + 1) * 136 + m] = __float2half_rn(acc[mb][nb][1]);
            ksth[n * 136 + m + 8] = __float2half_rn(acc[mb][nb][2]);
            ksth[(n + 1) * 136 + m + 8] = __float2half_rn(acc[mb][nb][3]);
        }
    __syncthreads();

    {
        const int h = wid;
        const int c = lid >> 1;
        const int d0 = (lid & 1) * 8;
        float a8[8] = {0, 0, 0, 0, 0, 0, 0, 0};
        float sq = 0.f, sk8[8] = {0, 0, 0, 0, 0, 0, 0, 0};
#pragma unroll 4
        for (int n = 0; n < 128; n++) {
            float qv = __half2float(qsth[n * 136 + h * 16 + c]);
            uint4 kvu = *(const uint4*)&ksth[n * 136 + h * 16 + d0];
            __half2* kh2 = (__half2*)&kvu;
            float2 k01 = __half22float2(kh2[0]);
            float2 k23 = __half22float2(kh2[1]);
            float2 k45 = __half22float2(kh2[2]);
            float2 k67 = __half22float2(kh2[3]);
            a8[0] += qv * k01.x; a8[1] += qv * k01.y;
            a8[2] += qv * k23.x; a8[3] += qv * k23.y;
            a8[4] += qv * k45.x; a8[5] += qv * k45.y;
            a8[6] += qv * k67.x; a8[7] += qv * k67.y;
            if ((lid & 1) == 0) sq += qv * qv;
            if (c == 0) {
                sk8[0] += k01.x * k01.x; sk8[1] += k01.y * k01.y;
                sk8[2] += k23.x * k23.x; sk8[3] += k23.y * k23.y;
                sk8[4] += k45.x * k45.x; sk8[5] += k45.y * k45.y;
                sk8[6] += k67.x * k67.x; sk8[7] += k67.y * k67.y;
            }
        }
        const int bh = b * HEADS + h;
#pragma unroll
        for (int j = 0; j < 8; j++)
            atomicAdd(&G[(size_t)bh * 256 + c * 16 + d0 + j], a8[j]);
        if ((lid & 1) == 0) atomicAdd(&SQ[bh * 16 + c], sq);
        if (c == 0)
#pragma unroll
            for (int j = 0; j < 8; j++) atomicAdd(&SK[bh * 16 + d0 + j], sk8[j]);
    }
}

// ---------------- prep: weight splits + zero stats in one launch ----------
__device__ __forceinline__ void split_store(const float4& v, f16* hi, f16* lo, int i) {
    float a[4] = {v.x, v.y, v.z, v.w};
    f16 h[4], l[4];
#pragma unroll
    for (int j = 0; j < 4; j++) {
        h[j] = __float2half_rn(a[j]);
        l[j] = __float2half_rn(a[j] - __half2float(h[j]));
    }
    ((uint2*)hi)[i] = *(uint2*)h;
    ((uint2*)lo)[i] = *(uint2*)l;
}

__global__ void prep_all(const float* __restrict__ wqkv, const float* __restrict__ wq,
                         const float* __restrict__ wk,
                         f16* __restrict__ qkvh, f16* __restrict__ qkvl,
                         f16* __restrict__ qh, f16* __restrict__ ql,
                         f16* __restrict__ kh, f16* __restrict__ kl,
                         float* __restrict__ G, float* __restrict__ SQ,
                         float* __restrict__ SK) {
    int i = blockIdx.x * 256 + threadIdx.x;
    int y = blockIdx.y;
    const int n4 = C3 * CB / 4;
    if (y == 0) {
        if (i < n4) split_store(((const float4*)wqkv)[i], qkvh, qkvl, i);
    } else if (y == 1) {
        if (i < n4) split_store(((const float4*)wq)[i], qh, ql, i);
    } else if (y == 2) {
        if (i < n4) split_store(((const float4*)wk)[i], kh, kl, i);
    } else {
        if (i < BATCH * HEADS * 256) G[i] = 0.f;
        if (i < BATCH * HEADS * 16) { SQ[i] = 0.f; SK[i] = 0.f; }
    }
}

// ----- dwconv: scalar FFMA, 2-row blocking (measured best: 331 us) ----------
__global__ void __launch_bounds__(256)
dwconv_kernel(const f16* __restrict__ xq, const float* __restrict__ w3,
              const float* __restrict__ w5, const float* __restrict__ w7,
              f16* __restrict__ D) {
    __shared__ float tile[38][72];
    __shared__ float s3[9], s5[25], s7[49];

    const int bc = blockIdx.z;
    const int b = bc / C3, c = bc % C3;
    const int x0 = blockIdx.x * 64, y0 = blockIdx.y * 32;
    const int tid = threadIdx.x;

    const f16* src = xq + (size_t)bc * HWSZ;
    if (tid < 9)  s3[tid] = w3[c * 9 + tid];
    if (tid < 25) s5[tid] = w5[c * 25 + tid];
    if (tid < 49) s7[tid] = w7[c * 49 + tid];

    for (int e = tid; e < 38 * 70; e += 256) {
        int iy = e / 70, ix = e % 70;
        int gy = y0 - 3 + iy, gx = x0 - 3 + ix;
        float v = 0.f;
        if (gy >= 0 && gy < IMG && gx >= 0 && gx < IMG) v = __half2float(src[gy * IMG + gx]);
        tile[iy][ix] = v;
    }
    __syncthreads();

    const int tx = (tid & 15) * 4;
    const int ty = (tid >> 4) * 2;

    float a3[2][4], a5[2][4], a7[2][4];
#pragma unroll
    for (int r = 0; r < 2; r++)
#pragma unroll
        for (int xi = 0; xi < 4; xi++) { a3[r][xi] = 0.f; a5[r][xi] = 0.f; a7[r][xi] = 0.f; }

#pragma unroll
    for (int iy = 0; iy < 8; iy++) {
        float rr[10];
#pragma unroll
        for (int j = 0; j < 10; j++) rr[j] = tile[ty + iy][tx + j];
#pragma unroll
        for (int orow = 0; orow < 2; orow++) {
            const int ky = iy - orow;
            if (ky >= 0 && ky <= 6) {
#pragma unroll
                for (int kx = 0; kx < 7; kx++) {
                    float w = s7[ky * 7 + kx];
#pragma unroll
                    for (int xi = 0; xi < 4; xi++) a7[orow][xi] += rr[kx + xi] * w;
                }
                if (ky >= 1 && ky <= 5) {
#pragma unroll
                    for (int kx = 0; kx < 5; kx++) {
                        float w = s5[(ky - 1) * 5 + kx];
#pragma unroll
                        for (int xi = 0; xi < 4; xi++) a5[orow][xi] += rr[kx + 1 + xi] * w;
                    }
                }
                if (ky >= 2 && ky <= 4) {
#pragma unroll
                    for (int kx = 0; kx < 3; kx++) {
                        float w = s3[(ky - 2) * 3 + kx];
#pragma unroll
                        for (int xi = 0; xi < 4; xi++) a3[orow][xi] += rr[kx + 2 + xi] * w;
                    }
                }
            }
        }
    }

#pragma unroll
    for (int orow = 0; orow < 2; orow++) {
        size_t o = ((size_t)b * 3 * C3 + c) * HWSZ +
                   (size_t)(y0 + ty + orow) * IMG + (x0 + tx);
        f16 h3[4] = {__float2half_rn(a3[orow][0]), __float2half_rn(a3[orow][1]),
                     __float2half_rn(a3[orow][2]), __float2half_rn(a3[orow][3])};
        f16 h5[4] = {__float2half_rn(a5[orow][0]), __float2half_rn(a5[orow][1]),
                     __float2half_rn(a5[orow][2]), __float2half_rn(a5[orow][3])};
        f16 h7[4] = {__float2half_rn(a7[orow][0]), __float2half_rn(a7[orow][1]),
                     __float2half_rn(a7[orow][2]), __float2half_rn(a7[orow][3])};
        *(uint2*)&D[o] = *(uint2*)h3;
        *(uint2*)&D[o + (size_t)C3 * HWSZ] = *(uint2*)h5;
        *(uint2*)&D[o + (size_t)2 * C3 * HWSZ] = *(uint2*)h7;
    }
}

// ---- T1 with inline softmax: T1[b,m,r] = sum_d softmax_row(d) * wv[...] ----
__global__ void t1_kernel(const float* __restrict__ G, const float* __restrict__ SQ,
                          const float* __restrict__ SK, const float* __restrict__ temp,
                          const float* __restrict__ wv, float* __restrict__ T1) {
    const int bm = blockIdx.x, b = bm >> 7, m = bm & 127, h = m >> 4, cm = m & 15;
    const int bh = b * HEADS + h;
    __shared__ float a[16];
    if (threadIdx.x < 16) {
        // compute softmax row (bh, cm, :) inline
        float nq = fmaxf(sqrtf(SQ[bh * 16 + cm]), 1e-12f);
        float t = temp[h];
        // each of 16 threads computes one scaled score; then block softmax
        __shared__ float s[16];
        int d = threadIdx.x;
        float nk = fmaxf(sqrtf(SK[bh * 16 + d]), 1e-12f);
        s[d] = G[(size_t)bh * 256 + cm * 16 + d] / (nq * nk) * t;
        __syncwarp(0xFFFF);
        float mx = -1e30f, sum = 0.f;
#pragma unroll
        for (int j = 0; j < 16; j++) mx = fmaxf(mx, s[j]);
        float e = expf(s[d] - mx);
        a[d] = e;
        __syncwarp(0xFFFF);
#pragma unroll
        for (int j = 0; j < 16; j++) sum += a[j];
        a[d] = e / sum;
    }
    __syncthreads();
    const int r = threadIdx.x;
    float acc = 0.f;
#pragma unroll
    for (int d = 0; d < 16; d++) acc += a[d] * wv[(h * 16 + d) * C3 + r];
    T1[((size_t)b * CB + m) * C3 + r] = acc;
}

// ---- M with inline fp16 split: Mh/Ml[b,o,r] = split(sum_m wout[o,m]*T1) ----
__global__ void m_kernel(const float* __restrict__ wout, const float* __restrict__ T1,
                         f16* __restrict__ Mh, f16* __restrict__ Ml) {
    const int bo = blockIdx.x, b = bo >> 7, o = bo & 127;
    __shared__ float w[128];
    if (threadIdx.x < 128) w[threadIdx.x] = wout[o * 128 + threadIdx.x];
    __syncthreads();
    const int r = threadIdx.x;
    float acc = 0.f;
#pragma unroll 8
    for (int m = 0; m < 128; m++) acc += w[m] * T1[((size_t)b * CB + m) * C3 + r];
    f16 hi = __float2half_rn(acc);
    f16 lo = __float2half_rn(acc - __half2float(hi));
    size_t idx = ((size_t)b * CB + o) * C3 + r;
    Mh[idx] = hi;
    Ml[idx] = lo;
}

// ---------------- host launcher ----------------
extern "C" void kernel_launch(void* const* d_in, const int* in_sizes, int n_in,
                              void* d_out, int out_size) {
    const float* x     = (const float*)d_in[0];
    const float* w_qkv = (const float*)d_in[1];
    const float* w_dw3 = (const float*)d_in[2];
    const float* w_dw5 = (const float*)d_in[3];
    const float* w_dw7 = (const float*)d_in[4];
    const float* w_q   = (const float*)d_in[5];
    const float* w_k   = (const float*)d_in[6];
    const float* w_v   = (const float*)d_in[7];
    const float* w_out = (const float*)d_in[8];
    const float* temp  = (const float*)d_in[9];
    float* out = (float*)d_out;

    float *p_gram, *p_ssq, *p_ssk, *p_T1;
    f16 *p_xq16, *p_D16, *p_wqkvh, *p_wqkvl, *p_wqh, *p_wql, *p_wkh, *p_wkl, *p_Mh, *p_Ml;
    cudaGetSymbolAddress((void**)&p_xq16, g_xq16);
    cudaGetSymbolAddress((void**)&p_D16, g_D16);
    cudaGetSymbolAddress((void**)&p_gram, g_gram);
    cudaGetSymbolAddress((void**)&p_ssq, g_ssq);
    cudaGetSymbolAddress((void**)&p_ssk, g_ssk);
    cudaGetSymbolAddress((void**)&p_T1, g_T1);
    cudaGetSymbolAddress((void**)&p_wqkvh, g_wqkv_h);
    cudaGetSymbolAddress((void**)&p_wqkvl, g_wqkv_l);
    cudaGetSymbolAddress((void**)&p_wqh, g_wq_h);
    cudaGetSymbolAddress((void**)&p_wql, g_wq_l);
    cudaGetSymbolAddress((void**)&p_wkh, g_wk_h);
    cudaGetSymbolAddress((void**)&p_wkl, g_wk_l);
    cudaGetSymbolAddress((void**)&p_Mh, g_Mh);
    cudaGetSymbolAddress((void**)&p_Ml, g_Ml);

    cudaFuncSetAttribute(tc_gemm_f32, cudaFuncAttributeMaxDynamicSharedMemorySize, STG_BYTES);
    cudaFuncSetAttribute(tc_gemm_f16_bf32, cudaFuncAttributeMaxDynamicSharedMemorySize, STG_BYTES);
    cudaFuncSetAttribute(qk_gram, cudaFuncAttributeMaxDynamicSharedMemorySize, QKG_BYTES);

    // 0) merged prep: weight splits + stat zeroing
    prep_all<<<dim3(64, 4), 256>>>(w_qkv, w_q, w_k, p_wqkvh, p_wqkvl,
                                   p_wqh, p_wql, p_wkh, p_wkl,
                                   p_gram, p_ssq, p_ssk);

    // 1) xq = w_qkv @ x
    tc_gemm_f16_bf32<<<dim3(3, 128, BATCH), 256, STG_BYTES>>>(
        p_wqkvh, p_wqkvl, 128, (size_t)0,
        x, (size_t)CB * HWSZ, (size_t)CB * HWSZ,
        p_xq16, (size_t)C3 * HWSZ);

    // 2) depthwise conv -> D fp16
    dwconv_kernel<<<dim3(2, 4, BATCH * C3), 256>>>(p_xq16, w_dw3, w_dw5, w_dw7, p_D16);

    // 3) fused q/k projections + gram + sumsq
    qk_gram<<<dim3(128, BATCH), 256, QKG_BYTES>>>(
        p_wqh, p_wql, p_wkh, p_wkl, p_D16, p_gram, p_ssq, p_ssk);

    // 4) T1 (softmax inline), M (fp16 split inline)
    t1_kernel<<<BATCH * CB, 384>>>(p_gram, p_ssq, p_ssk, temp, w_v, p_T1);
    m_kernel<<<BATCH * CB, 384>>>(w_out, p_T1, p_Mh, p_Ml);

    // 5) out = M_b @ D(v-part)
    tc_gemm_f32<<<dim3(1, 128, BATCH), 256, STG_BYTES>>>(
        p_Mh, p_Ml, 384, (size_t)CB * C3,
        p_D16 + (size_t)2 * CB * HWSZ, (size_t)3 * C3 * HWSZ, (size_t)C3 * HWSZ,
        out, (size_t)CB * HWSZ);
}